// round 2
// baseline (speedup 1.0000x reference)
#include <cuda_runtime.h>
#include <cuda_bf16.h>
#include <math.h>

// Problem constants
#define B_  8
#define C_  256
#define T_  8
#define H_  56
#define W_  56
#define HW_ (H_*W_)
#define CR_ 64

// Scratch (device globals: sanctioned workaround for no-alloc rule)
__device__ float  g_pool[B_*C_*T_];           // [b][c][t]
__device__ float  g_walpha[B_*C_*T_];         // [b][c][t]
__device__ float  g_balpha[B_*C_*T_];         // [b][c][t]
__device__ float  g_conv[(size_t)B_*C_*T_*HW_]; // conv output, pre-BN
__device__ double g_stats[C_][4];             // sum, sumsq, sum_ap, sumsq_ap

// ---------------------------------------------------------------------------
// Kernel 1: spatial mean pool  feat[b,c,t,:,:] -> g_pool[b,c,t]
// ---------------------------------------------------------------------------
__global__ void pool_kernel(const float* __restrict__ feat) {
    int bct = blockIdx.x;                 // (b*256+c)*8+t
    const float* p = feat + (size_t)bct * HW_;
    float s = 0.f;
    for (int i = threadIdx.x; i < HW_; i += blockDim.x) s += p[i];
    // reduce
    for (int o = 16; o; o >>= 1) s += __shfl_down_sync(0xffffffffu, s, o);
    __shared__ float sb[8];
    int lane = threadIdx.x & 31, w = threadIdx.x >> 5;
    if (lane == 0) sb[w] = s;
    __syncthreads();
    if (threadIdx.x == 0) {
        float t = 0.f;
        int nw = blockDim.x >> 5;
        for (int i = 0; i < nw; i++) t += sb[i];
        g_pool[bct] = t * (1.f / HW_);
    }
}

// ---------------------------------------------------------------------------
// Kernel 2: routing network, one block per batch b (256 threads)
// produces g_walpha, g_balpha
// ---------------------------------------------------------------------------
__device__ __forceinline__ float qgelu(float x) {
    return x / (1.f + __expf(-1.702f * x));
}

__global__ void routing_kernel(
    const float* __restrict__ a_w, const float* __restrict__ a_b,
    const float* __restrict__ norm_w, const float* __restrict__ norm_b,
    const float* __restrict__ normt_w, const float* __restrict__ normt_b,
    const float* __restrict__ qkv_w, const float* __restrict__ qkv_b,
    const float* __restrict__ ao_w, const float* __restrict__ ao_b,
    const float* __restrict__ b_w, const float* __restrict__ bb_w)
{
    int b = blockIdx.x;
    int tid = threadIdx.x;

    __shared__ float s_pool[C_][T_];
    __shared__ float s_x1[CR_][T_];
    __shared__ float s_x2[CR_][T_];
    __shared__ float s_xn[CR_][T_];
    __shared__ float s_qkv[3*CR_][T_];
    __shared__ float s_att[T_][T_];
    __shared__ float s_o[CR_][T_];
    __shared__ float s_mu[T_], s_rstd[T_];

    for (int i = tid; i < C_*T_; i += 256) s_pool[i >> 3][i & 7] = g_pool[b*C_*T_ + i];
    __syncthreads();

    // conv 'a' : [64][8]
    for (int idx = tid; idx < CR_*T_; idx += 256) {
        int r = idx >> 3, t = idx & 7;
        float acc = a_b[r];
        const float* wbase = a_w + (size_t)r * C_ * 3;
        for (int c = 0; c < C_; c++) {
            float p0 = (t > 0) ? s_pool[c][t-1] : 0.f;
            float p1 = s_pool[c][t];
            float p2 = (t < 7) ? s_pool[c][t+1] : 0.f;
            const float* w = wbase + c*3;
            acc += w[0]*p0 + w[1]*p1 + w[2]*p2;
        }
        s_x1[r][t] = acc;
    }
    __syncthreads();

    // LN over channel (64) per t  + qGELU  -> s_x2
    if (tid < T_) {
        int t = tid;
        float mu = 0.f;
        for (int r = 0; r < CR_; r++) mu += s_x1[r][t];
        mu *= (1.f / CR_);
        float v = 0.f;
        for (int r = 0; r < CR_; r++) { float d = s_x1[r][t] - mu; v += d*d; }
        v *= (1.f / CR_);
        s_mu[t] = mu; s_rstd[t] = rsqrtf(v + 1e-6f);
    }
    __syncthreads();
    for (int idx = tid; idx < CR_*T_; idx += 256) {
        int r = idx >> 3, t = idx & 7;
        float xln = (s_x1[r][t] - s_mu[t]) * s_rstd[t] * norm_w[r] + norm_b[r];
        s_x2[r][t] = qgelu(xln);
    }
    __syncthreads();

    // second LN -> s_xn
    if (tid < T_) {
        int t = tid;
        float mu = 0.f;
        for (int r = 0; r < CR_; r++) mu += s_x2[r][t];
        mu *= (1.f / CR_);
        float v = 0.f;
        for (int r = 0; r < CR_; r++) { float d = s_x2[r][t] - mu; v += d*d; }
        v *= (1.f / CR_);
        s_mu[t] = mu; s_rstd[t] = rsqrtf(v + 1e-6f);
    }
    __syncthreads();
    for (int idx = tid; idx < CR_*T_; idx += 256) {
        int r = idx >> 3, t = idx & 7;
        s_xn[r][t] = (s_x2[r][t] - s_mu[t]) * s_rstd[t] * normt_w[r] + normt_b[r];
    }
    __syncthreads();

    // qkv: [192][8]
    for (int idx = tid; idx < 3*CR_*T_; idx += 256) {
        int o = idx >> 3, t = idx & 7;
        float acc = qkv_b[o];
        const float* w = qkv_w + (size_t)o * CR_;
        for (int c = 0; c < CR_; c++) acc += w[c] * s_xn[c][t];
        s_qkv[o][t] = acc;
    }
    __syncthreads();

    // attention scores (1 head, hd=64): s[i][j] = 0.125 * sum_d q[d][i]*k[d][j]
    if (tid < T_*T_) {
        int i = tid >> 3, j = tid & 7;
        float a = 0.f;
        for (int d = 0; d < CR_; d++) a += s_qkv[d][i] * s_qkv[CR_ + d][j];
        s_att[i][j] = a * 0.125f;  // 64^{-1/2}
    }
    __syncthreads();
    if (tid < T_) {
        int i = tid;
        float m = -1e30f;
        for (int j = 0; j < T_; j++) m = fmaxf(m, s_att[i][j]);
        float sum = 0.f;
        for (int j = 0; j < T_; j++) { float e = __expf(s_att[i][j] - m); s_att[i][j] = e; sum += e; }
        float inv = 1.f / sum;
        for (int j = 0; j < T_; j++) s_att[i][j] *= inv;
    }
    __syncthreads();
    // o[d][t] = sum_j att[t][j] * v[d][j]
    for (int idx = tid; idx < CR_*T_; idx += 256) {
        int d = idx >> 3, t = idx & 7;
        float a = 0.f;
        for (int j = 0; j < T_; j++) a += s_att[t][j] * s_qkv[2*CR_ + d][j];
        s_o[d][t] = a;
    }
    __syncthreads();
    // ao proj + residual -> reuse s_x1 as x3
    for (int idx = tid; idx < CR_*T_; idx += 256) {
        int r = idx >> 3, t = idx & 7;
        float acc = ao_b[r];
        const float* w = ao_w + (size_t)r * CR_;
        for (int c = 0; c < CR_; c++) acc += w[c] * s_o[c][t];
        s_x1[r][t] = s_x2[r][t] + acc;
    }
    __syncthreads();

    // w_alpha / b_alpha: [256][8] each, conv1d k=3 pad=1 over t, no bias
    for (int idx = tid; idx < C_*T_; idx += 256) {
        int Co = idx >> 3, t = idx & 7;
        float aw = 0.f, ab = 0.f;
        const float* w1base = b_w  + (size_t)Co * CR_ * 3;
        const float* w2base = bb_w + (size_t)Co * CR_ * 3;
        for (int r = 0; r < CR_; r++) {
            float x0 = (t > 0) ? s_x1[r][t-1] : 0.f;
            float x1 = s_x1[r][t];
            float x2 = (t < 7) ? s_x1[r][t+1] : 0.f;
            const float* w1 = w1base + r*3;
            const float* w2 = w2base + r*3;
            aw += w1[0]*x0 + w1[1]*x1 + w1[2]*x2;
            ab += w2[0]*x0 + w2[1]*x1 + w2[2]*x2;
        }
        g_walpha[b*C_*T_ + idx] = aw;
        g_balpha[b*C_*T_ + idx] = ab;
    }
}

// ---------------------------------------------------------------------------
// Kernel 3: calibrated 3x3 conv.
// grid: x = h-tile (7 tiles of 8 rows), y = o-group (16 groups of 16),
//       z = b*t (64). block: 224 threads.
// thread: othr = tid/112 (8 o each), spatial 2x2 pixels.
// ---------------------------------------------------------------------------
#define CCHUNK 4
__global__ void __launch_bounds__(224)
conv_kernel(const float* __restrict__ feat, const float* __restrict__ Wt,
            const float* __restrict__ bias_p)
{
    int bt = blockIdx.z;
    int b  = bt >> 3, t = bt & 7;
    int og = blockIdx.y;        // output-channel group (16 ch)
    int yt = blockIdx.x;        // row tile (8 rows)
    int tid = threadIdx.x;
    int othr = tid / 112;       // 0..1
    int sp   = tid % 112;
    int sx = sp % 28;           // 0..27 (column pair)
    int sy = sp / 28;           // 0..3  (row pair)
    int px = 2*sx;
    int py = yt*8 + 2*sy;

    __shared__ float s_in[CCHUNK][10][58];
    __shared__ float s_w[16][CCHUNK][9];

    float acc[8][2][2] = {};

    const size_t cstride = (size_t)T_ * HW_;
    const float* fbase = feat + ((size_t)b * C_ * T_ + t) * HW_;
    const float* wa    = g_walpha + b*C_*T_ + t;     // + c*8

    for (int c0 = 0; c0 < C_; c0 += CCHUNK) {
        // load scaled input tile: CCHUNK x 10 x 58
        for (int idx = tid; idx < CCHUNK*10*58; idx += 224) {
            int cc  = idx / 580;
            int rem = idx % 580;
            int ly  = rem / 58;
            int lx  = rem % 58;
            int gy = yt*8 + ly - 1;
            int gx = lx - 1;
            float v = 0.f;
            if (gy >= 0 && gy < H_ && gx >= 0 && gx < W_) {
                v = fbase[(size_t)(c0+cc)*cstride + gy*W_ + gx] * wa[(c0+cc)*T_];
            }
            s_in[cc][ly][lx] = v;
        }
        // load weights: 16 x CCHUNK x 9
        for (int idx = tid; idx < 16*CCHUNK*9; idx += 224) {
            int oo  = idx / (CCHUNK*9);
            int rem = idx % (CCHUNK*9);
            int cc  = rem / 9;
            int k   = rem % 9;
            s_w[oo][cc][k] = Wt[((size_t)(og*16 + oo) * C_ + c0 + cc) * 9 + k];
        }
        __syncthreads();

        #pragma unroll
        for (int cc = 0; cc < CCHUNK; cc++) {
            float in[4][4];
            #pragma unroll
            for (int r = 0; r < 4; r++)
                #pragma unroll
                for (int cI = 0; cI < 4; cI++)
                    in[r][cI] = s_in[cc][2*sy + r][2*sx + cI];

            #pragma unroll
            for (int oo = 0; oo < 8; oo++) {
                const float* wp = &s_w[othr*8 + oo][cc][0];
                float w0 = wp[0], w1 = wp[1], w2 = wp[2];
                float w3 = wp[3], w4 = wp[4], w5 = wp[5];
                float w6 = wp[6], w7 = wp[7], w8 = wp[8];
                #pragma unroll
                for (int dy = 0; dy < 2; dy++)
                    #pragma unroll
                    for (int dx = 0; dx < 2; dx++) {
                        float a = acc[oo][dy][dx];
                        a = fmaf(w0, in[dy  ][dx  ], a);
                        a = fmaf(w1, in[dy  ][dx+1], a);
                        a = fmaf(w2, in[dy  ][dx+2], a);
                        a = fmaf(w3, in[dy+1][dx  ], a);
                        a = fmaf(w4, in[dy+1][dx+1], a);
                        a = fmaf(w5, in[dy+1][dx+2], a);
                        a = fmaf(w6, in[dy+2][dx  ], a);
                        a = fmaf(w7, in[dy+2][dx+1], a);
                        a = fmaf(w8, in[dy+2][dx+2], a);
                        acc[oo][dy][dx] = a;
                    }
            }
        }
        __syncthreads();
    }

    // epilogue: bias + store to scratch
    #pragma unroll
    for (int oo = 0; oo < 8; oo++) {
        int o = og*16 + othr*8 + oo;
        float bias = g_balpha[b*C_*T_ + o*T_ + t] * bias_p[o];
        size_t obase = (((size_t)b*C_ + o)*T_ + t) * HW_;
        #pragma unroll
        for (int dy = 0; dy < 2; dy++)
            #pragma unroll
            for (int dx = 0; dx < 2; dx++)
                g_conv[obase + (py+dy)*W_ + (px+dx)] = acc[oo][dy][dx] + bias;
    }
}

// ---------------------------------------------------------------------------
// Kernel 4a: zero stats
// ---------------------------------------------------------------------------
__global__ void zero_stats_kernel() {
    int i = threadIdx.x + blockIdx.x * blockDim.x;
    if (i < C_*4) ((double*)g_stats)[i] = 0.0;
}

// ---------------------------------------------------------------------------
// Kernel 4: per-channel stats of conv output and its temporal 3-tap average
// grid: (98, 256 channels), 256 threads; each thread: fixed (b,hw), loop t.
// ---------------------------------------------------------------------------
__global__ void stats_kernel() {
    int c = blockIdx.y;
    int item = blockIdx.x * blockDim.x + threadIdx.x;   // 0..25087
    int b  = item / HW_;
    int hw = item % HW_;

    size_t base = (((size_t)b*C_ + c)*T_) * HW_ + hw;
    float so = 0.f, sq = 0.f, sa = 0.f, sqa = 0.f;
    float prev = 0.f;
    float cur  = g_conv[base];
    #pragma unroll
    for (int t = 0; t < T_; t++) {
        float next = (t < T_-1) ? g_conv[base + (size_t)(t+1)*HW_] : 0.f;
        so += cur;
        sq += cur*cur;
        float ap = (prev + cur + next) * (1.f/3.f);
        sa  += ap;
        sqa += ap*ap;
        prev = cur; cur = next;
    }

    // block reduce 4 floats
    __shared__ float sb[4][8];
    #pragma unroll
    for (int o = 16; o; o >>= 1) {
        so  += __shfl_down_sync(0xffffffffu, so,  o);
        sq  += __shfl_down_sync(0xffffffffu, sq,  o);
        sa  += __shfl_down_sync(0xffffffffu, sa,  o);
        sqa += __shfl_down_sync(0xffffffffu, sqa, o);
    }
    int lane = threadIdx.x & 31, w = threadIdx.x >> 5;
    if (lane == 0) { sb[0][w] = so; sb[1][w] = sq; sb[2][w] = sa; sb[3][w] = sqa; }
    __syncthreads();
    if (threadIdx.x == 0) {
        float a0=0, a1=0, a2=0, a3=0;
        for (int i = 0; i < 8; i++) { a0+=sb[0][i]; a1+=sb[1][i]; a2+=sb[2][i]; a3+=sb[3][i]; }
        atomicAdd(&g_stats[c][0], (double)a0);
        atomicAdd(&g_stats[c][1], (double)a1);
        atomicAdd(&g_stats[c][2], (double)a2);
        atomicAdd(&g_stats[c][3], (double)a3);
    }
}

// ---------------------------------------------------------------------------
// Kernel 5: final  out = bn_a(conv) + bn_b(avgpool_t3(conv))
// ---------------------------------------------------------------------------
__global__ void final_kernel(const float* __restrict__ gamma_a, const float* __restrict__ beta_a,
                             const float* __restrict__ gamma_b, const float* __restrict__ beta_b,
                             float* __restrict__ out)
{
    int c = blockIdx.y;
    int item = blockIdx.x * blockDim.x + threadIdx.x;
    int b  = item / HW_;
    int hw = item % HW_;

    const double N = (double)B_ * T_ * HW_;
    double mu_a = g_stats[c][0] / N;
    double va   = g_stats[c][1] / N - mu_a*mu_a;
    double mu_b = g_stats[c][2] / N;
    double vb   = g_stats[c][3] / N - mu_b*mu_b;
    float sca = gamma_a[c] * (float)(1.0 / sqrt(va + 1e-5));
    float sha = beta_a[c] - (float)mu_a * sca;
    float scb = gamma_b[c] * (float)(1.0 / sqrt(vb + 1e-5));
    float shb = beta_b[c] - (float)mu_b * scb;

    size_t base = (((size_t)b*C_ + c)*T_) * HW_ + hw;
    float prev = 0.f;
    float cur  = g_conv[base];
    #pragma unroll
    for (int t = 0; t < T_; t++) {
        float next = (t < T_-1) ? g_conv[base + (size_t)(t+1)*HW_] : 0.f;
        float ap = (prev + cur + next) * (1.f/3.f);
        out[base + (size_t)t*HW_] = cur*sca + sha + ap*scb + shb;
        prev = cur; cur = next;
    }
}

// ---------------------------------------------------------------------------
extern "C" void kernel_launch(void* const* d_in, const int* in_sizes, int n_in,
                              void* d_out, int out_size)
{
    const float* feat    = (const float*)d_in[0];
    const float* Wt      = (const float*)d_in[1];
    const float* bias_p  = (const float*)d_in[2];
    const float* a_w     = (const float*)d_in[3];
    const float* a_b     = (const float*)d_in[4];
    const float* norm_w  = (const float*)d_in[5];
    const float* norm_b  = (const float*)d_in[6];
    const float* normt_w = (const float*)d_in[7];
    const float* normt_b = (const float*)d_in[8];
    const float* qkv_w   = (const float*)d_in[9];
    const float* qkv_b   = (const float*)d_in[10];
    const float* ao_w    = (const float*)d_in[11];
    const float* ao_b    = (const float*)d_in[12];
    const float* b_w     = (const float*)d_in[13];
    const float* bb_w    = (const float*)d_in[14];
    const float* gamma_a = (const float*)d_in[15];
    const float* beta_a  = (const float*)d_in[16];
    const float* gamma_b = (const float*)d_in[17];
    const float* beta_b  = (const float*)d_in[18];
    float* out = (float*)d_out;

    pool_kernel<<<B_*C_*T_, 128>>>(feat);
    routing_kernel<<<B_, 256>>>(a_w, a_b, norm_w, norm_b, normt_w, normt_b,
                                qkv_w, qkv_b, ao_w, ao_b, b_w, bb_w);
    conv_kernel<<<dim3(7, 16, 64), 224>>>(feat, Wt, bias_p);
    zero_stats_kernel<<<4, 256>>>();
    stats_kernel<<<dim3(98, 256), 256>>>();
    final_kernel<<<dim3(98, 256), 256>>>(gamma_a, beta_a, gamma_b, beta_b, out);
}